// round 4
// baseline (speedup 1.0000x reference)
#include <cuda_runtime.h>
#include <cuda_bf16.h>

#define IMG_H 480
#define IMG_W 640
#define HW (IMG_H * IMG_W)          // 307200
#define CHW (3 * HW)
#define QPP (HW / 4)                // float4 quads per plane = 76800
#define MAX_B 64
#define NBLOCKS 148
#define NTHREADS 512

// Scratch (device globals per harness rules). Partials overwritten each run —
// no zeroing pass required. Barrier generation counter survives replays by design.
__device__ float g_partial[NBLOCKS * MAX_B];
__device__ unsigned g_bar_count = 0;
__device__ unsigned g_bar_gen = 0;

__device__ __forceinline__ void process_px(float& r, float& g, float& b,
                                           float B, float C, float S,
                                           float hfv, float m) {
    r = __saturatef(r * B);
    g = __saturatef(g * B);
    b = __saturatef(b * B);
    const float omC = 1.0f - C;
    r = __saturatef(C * r + omC * m);
    g = __saturatef(C * g + omC * m);
    b = __saturatef(C * b + omC * m);
    const float gray = 0.299f * r + 0.587f * g + 0.114f * b;
    const float omS = 1.0f - S;
    r = __saturatef(S * r + omS * gray);
    g = __saturatef(S * g + omS * gray);
    b = __saturatef(S * b + omS * gray);
    const float maxc = fmaxf(r, fmaxf(g, b));
    const float minc = fminf(r, fminf(g, b));
    const float v = maxc;
    const float cr = maxc - minc;
    const float crd = (cr == 0.0f) ? 1.0f : cr;
    const float s = cr / ((maxc == 0.0f) ? 1.0f : maxc);
    const float inv_crd = 1.0f / crd;
    const float rc = (maxc - r) * inv_crd;
    const float gc = (maxc - g) * inv_crd;
    const float bc = (maxc - b) * inv_crd;
    float h;
    if (maxc == r)      h = bc - gc;
    else if (maxc == g) h = 2.0f + rc - bc;
    else                h = 4.0f + gc - rc;
    h = h * (1.0f / 6.0f);
    h -= floorf(h);
    h += hfv;
    h -= floorf(h);
    const float i6 = h * 6.0f;
    const float fi = floorf(i6);
    const float f = i6 - fi;
    int i = ((int)fi) % 6;
    const float p = v * (1.0f - s);
    const float q = v * (1.0f - f * s);
    const float t = v * (1.0f - (1.0f - f) * s);
    switch (i) {
        case 0:  r = v; g = t; b = p; break;
        case 1:  r = q; g = v; b = p; break;
        case 2:  r = p; g = v; b = t; break;
        case 3:  r = p; g = q; b = v; break;
        case 4:  r = t; g = p; b = v; break;
        default: r = v; g = p; b = q; break;
    }
}

// Gray sum of one brightness-clipped quad (4 pixels).
__device__ __forceinline__ float quad_gray(const float4& r4, const float4& g4,
                                           const float4& b4, float B) {
    float s = 0.0f;
    float r, g, bl;
    #define ACC(comp) \
        r = __saturatef(r4.comp * B); \
        g = __saturatef(g4.comp * B); \
        bl = __saturatef(b4.comp * B); \
        s += 0.299f * r + 0.587f * g + 0.114f * bl;
    ACC(x) ACC(y) ACC(z) ACC(w)
    #undef ACC
    return s;
}

__global__ void __launch_bounds__(NTHREADS, 1)
cr_fused_kernel(const float* __restrict__ x,
                const float* __restrict__ bf, const float* __restrict__ cf,
                const float* __restrict__ sf, const float* __restrict__ hf,
                float* __restrict__ out, int nb) {
    const int tid = threadIdx.x;
    const int lane = tid & 31;
    const int T = nb * QPP;
    const int stride = NBLOCKS * NTHREADS;   // 75776
    const int start = blockIdx.x * NTHREADS + tid;

    __shared__ float s_acc[MAX_B];
    __shared__ float s_mean[MAX_B];
    if (tid < MAX_B) { s_acc[tid] = 0.0f; s_mean[tid] = 0.0f; }
    __syncthreads();

    // ---- Phase 1: per-batch gray sums (unroll x2 for MLP) ----
    for (int q0 = start; q0 < T; q0 += 2 * stride) {
        const int b0 = q0 / QPP;
        const int p0 = q0 - b0 * QPP;
        const float4* base0 = (const float4*)(x + (size_t)b0 * CHW);
        float4 r0 = base0[p0];
        float4 g0 = base0[p0 + QPP];
        float4 c0 = base0[p0 + 2 * QPP];

        const int q1 = q0 + stride;
        float4 r1, g1, c1;
        int b1 = 0;
        const bool has1 = (q1 < T);
        if (has1) {
            b1 = q1 / QPP;
            const int p1 = q1 - b1 * QPP;
            const float4* base1 = (const float4*)(x + (size_t)b1 * CHW);
            r1 = base1[p1];
            g1 = base1[p1 + QPP];
            c1 = base1[p1 + 2 * QPP];
        }

        float s0 = quad_gray(r0, g0, c0, bf[b0]);
        // b is warp-uniform (QPP % 32 == 0, warp-aligned indexing)
        #pragma unroll
        for (int o = 16; o > 0; o >>= 1) s0 += __shfl_xor_sync(0xFFFFFFFFu, s0, o);
        if (lane == 0) atomicAdd(&s_acc[b0], s0);

        if (has1) {
            float s1 = quad_gray(r1, g1, c1, bf[b1]);
            #pragma unroll
            for (int o = 16; o > 0; o >>= 1) s1 += __shfl_xor_sync(0xFFFFFFFFu, s1, o);
            if (lane == 0) atomicAdd(&s_acc[b1], s1);
        }
    }
    __syncthreads();

    // Publish this block's partial row.
    if (tid < MAX_B) g_partial[blockIdx.x * MAX_B + tid] = s_acc[tid];
    __threadfence();
    __syncthreads();

    // ---- Grid barrier (generation-based; all 148 blocks resident) ----
    if (tid == 0) {
        const unsigned my_gen = atomicAdd(&g_bar_gen, 0u);
        const unsigned ticket = atomicAdd(&g_bar_count, 1u);
        if (ticket == NBLOCKS - 1) {
            g_bar_count = 0;
            __threadfence();
            atomicAdd(&g_bar_gen, 1u);
        } else {
            while (atomicAdd(&g_bar_gen, 0u) == my_gen) { __nanosleep(64); }
        }
        __threadfence();
    }
    __syncthreads();

    // ---- Reduce partial table into per-batch means (every block, cheap) ----
    {
        const int b = tid & (MAX_B - 1);
        const int slice = tid >> 6;              // 8 slices
        float s = 0.0f;
        for (int i = slice; i < NBLOCKS; i += 8)
            s += g_partial[i * MAX_B + b];
        atomicAdd(&s_mean[b], s);
    }
    __syncthreads();

    // ---- Phase 2: full pipeline, streaming ----
    for (int q = start; q < T; q += stride) {
        const int b = q / QPP;
        const int p = q - b * QPP;
        const float4* inb = (const float4*)(x + (size_t)b * CHW);
        float4* outb = (float4*)(out + (size_t)b * CHW);

        const float B = bf[b];
        const float C = cf[b];
        const float S = sf[b];
        const float Hf = hf[b];
        const float m = s_mean[b] * (1.0f / (float)HW);

        float4 r4 = __ldcs(&inb[p]);
        float4 g4 = __ldcs(&inb[p + QPP]);
        float4 b4 = __ldcs(&inb[p + 2 * QPP]);

        process_px(r4.x, g4.x, b4.x, B, C, S, Hf, m);
        process_px(r4.y, g4.y, b4.y, B, C, S, Hf, m);
        process_px(r4.z, g4.z, b4.z, B, C, S, Hf, m);
        process_px(r4.w, g4.w, b4.w, B, C, S, Hf, m);

        __stcs(&outb[p],           r4);
        __stcs(&outb[p + QPP],     g4);
        __stcs(&outb[p + 2 * QPP], b4);
    }
}

extern "C" void kernel_launch(void* const* d_in, const int* in_sizes, int n_in,
                              void* d_out, int out_size) {
    const float* x  = (const float*)d_in[0];
    const float* bf = (const float*)d_in[1];
    const float* cf = (const float*)d_in[2];
    const float* sf = (const float*)d_in[3];
    const float* hf = (const float*)d_in[4];
    float* out = (float*)d_out;

    const int nb = out_size / CHW;  // num_samples is 1 by shape constraints

    cr_fused_kernel<<<NBLOCKS, NTHREADS>>>(x, bf, cf, sf, hf, out, nb);
}

// round 5
// speedup vs baseline: 1.5521x; 1.5521x over previous
#include <cuda_runtime.h>
#include <cuda_bf16.h>

#define IMG_H 480
#define IMG_W 640
#define HW (IMG_H * IMG_W)          // 307200
#define CHW (3 * HW)
#define QPP (HW / 4)                // float4 quads per plane = 76800
#define RED_THREADS 256
#define RED_BLOCKS_PER_PLANE (QPP / (RED_THREADS * 2))   // 150, exact (2 quads/thread)
#define MAIN_THREADS 256
#define MAIN_BLOCKS_PER_PLANE (QPP / MAIN_THREADS)       // 300, exact
#define MAX_B 64

// Scratch (device globals per harness rules).
// g_graysum starts zeroed (static init) and is re-zeroed by the LAST finishing
// block of the main kernel each run, so every launch/replay sees zeros.
__device__ float g_graysum[MAX_B];
__device__ unsigned g_fin = 0;

// Gray sum of one brightness-clipped quad (4 pixels).
__device__ __forceinline__ float quad_gray(const float4& r4, const float4& g4,
                                           const float4& b4, float B) {
    float s = 0.0f;
    float r, g, bl;
    #define ACC(comp) \
        r = __saturatef(r4.comp * B); \
        g = __saturatef(g4.comp * B); \
        bl = __saturatef(b4.comp * B); \
        s += 0.299f * r + 0.587f * g + 0.114f * bl;
    ACC(x) ACC(y) ACC(z) ACC(w)
    #undef ACC
    return s;
}

// Pass 1: per-batch sum of gray(clip(x * bf)). 2 quads per thread for MLP.
// Default cache policy so x becomes L2-resident for pass 2.
__global__ void __launch_bounds__(RED_THREADS)
cr_reduce_kernel(const float* __restrict__ x, const float* __restrict__ bf) {
    const int b = blockIdx.y;
    const int q0 = blockIdx.x * (RED_THREADS * 2) + threadIdx.x;  // exact fit
    const int q1 = q0 + RED_THREADS;
    const float4* base = (const float4*)(x + (size_t)b * CHW);

    const float B = bf[b];
    float4 r0 = base[q0];
    float4 g0 = base[q0 + QPP];
    float4 c0 = base[q0 + 2 * QPP];
    float4 r1 = base[q1];
    float4 g1 = base[q1 + QPP];
    float4 c1 = base[q1 + 2 * QPP];

    float s = quad_gray(r0, g0, c0, B) + quad_gray(r1, g1, c1, B);

    #pragma unroll
    for (int o = 16; o > 0; o >>= 1)
        s += __shfl_xor_sync(0xFFFFFFFFu, s, o);

    __shared__ float warp_s[RED_THREADS / 32];
    const int lane = threadIdx.x & 31;
    const int wid = threadIdx.x >> 5;
    if (lane == 0) warp_s[wid] = s;
    __syncthreads();
    if (wid == 0) {
        s = (lane < RED_THREADS / 32) ? warp_s[lane] : 0.0f;
        #pragma unroll
        for (int o = 4; o > 0; o >>= 1)
            s += __shfl_xor_sync(0xFFFFFFFFu, s, o);
        if (lane == 0) atomicAdd(&g_graysum[b], s);
    }
}

// Full per-pixel pipeline after the mean is known.
__device__ __forceinline__ void process_px(float& r, float& g, float& b,
                                           float B, float C, float S,
                                           float hfv, float m) {
    // brightness
    r = __saturatef(r * B);
    g = __saturatef(g * B);
    b = __saturatef(b * B);
    // contrast
    const float omC = 1.0f - C;
    r = __saturatef(C * r + omC * m);
    g = __saturatef(C * g + omC * m);
    b = __saturatef(C * b + omC * m);
    // saturation
    const float gray = 0.299f * r + 0.587f * g + 0.114f * b;
    const float omS = 1.0f - S;
    r = __saturatef(S * r + omS * gray);
    g = __saturatef(S * g + omS * gray);
    b = __saturatef(S * b + omS * gray);
    // hue rotation (reference branch structure preserved)
    const float maxc = fmaxf(r, fmaxf(g, b));
    const float minc = fminf(r, fminf(g, b));
    const float v = maxc;
    const float cr = maxc - minc;
    const float crd = (cr == 0.0f) ? 1.0f : cr;
    const float s = cr / ((maxc == 0.0f) ? 1.0f : maxc);
    const float inv_crd = 1.0f / crd;
    const float rc = (maxc - r) * inv_crd;
    const float gc = (maxc - g) * inv_crd;
    const float bc = (maxc - b) * inv_crd;
    float h;
    if (maxc == r)      h = bc - gc;
    else if (maxc == g) h = 2.0f + rc - bc;
    else                h = 4.0f + gc - rc;
    h = h * (1.0f / 6.0f);
    h -= floorf(h);
    h += hfv;
    h -= floorf(h);
    const float i6 = h * 6.0f;
    const float fi = floorf(i6);
    const float f = i6 - fi;
    int i = ((int)fi) % 6;
    const float p = v * (1.0f - s);
    const float q = v * (1.0f - f * s);
    const float t = v * (1.0f - (1.0f - f) * s);
    switch (i) {
        case 0:  r = v; g = t; b = p; break;
        case 1:  r = q; g = v; b = p; break;
        case 2:  r = p; g = v; b = t; break;
        case 3:  r = p; g = q; b = v; break;
        case 4:  r = t; g = p; b = v; break;
        default: r = v; g = p; b = q; break;
    }
}

// Pass 2: grid (MAIN_BLOCKS_PER_PLANE, nb) — exact fit, no div, no bounds
// check. __ldcs loads (last touch of x, L2-resident from pass 1), __stcs
// stores (never re-read). The LAST block to finish zeroes g_graysum and the
// finish counter for the next replay — all mean reads strictly precede it.
__global__ void __launch_bounds__(MAIN_THREADS)
cr_main_kernel(const float* __restrict__ x,
               const float* __restrict__ bf, const float* __restrict__ cf,
               const float* __restrict__ sf, const float* __restrict__ hf,
               float* __restrict__ out, unsigned total_blocks) {
    const int b = blockIdx.y;
    const int quad = blockIdx.x * MAIN_THREADS + threadIdx.x;

    const float4* inb = (const float4*)(x + (size_t)b * CHW);
    float4* outb = (float4*)(out + (size_t)b * CHW);

    const float B = bf[b];
    const float C = cf[b];
    const float S = sf[b];
    const float Hf = hf[b];
    const float m = g_graysum[b] * (1.0f / (float)HW);

    float4 r4 = __ldcs(&inb[quad]);
    float4 g4 = __ldcs(&inb[quad + QPP]);
    float4 b4 = __ldcs(&inb[quad + 2 * QPP]);

    process_px(r4.x, g4.x, b4.x, B, C, S, Hf, m);
    process_px(r4.y, g4.y, b4.y, B, C, S, Hf, m);
    process_px(r4.z, g4.z, b4.z, B, C, S, Hf, m);
    process_px(r4.w, g4.w, b4.w, B, C, S, Hf, m);

    __stcs(&outb[quad],           r4);
    __stcs(&outb[quad + QPP],     g4);
    __stcs(&outb[quad + 2 * QPP], b4);

    // ---- end-of-kernel state reset (replaces the zeroing kernel) ----
    __shared__ bool am_last;
    __syncthreads();                 // all threads' mean reads + work done
    if (threadIdx.x == 0) {
        __threadfence();
        const unsigned ticket = atomicAdd(&g_fin, 1u);
        am_last = (ticket == total_blocks - 1u);
    }
    __syncthreads();
    if (am_last) {
        if (threadIdx.x < MAX_B) g_graysum[threadIdx.x] = 0.0f;
        if (threadIdx.x == 0) g_fin = 0u;
    }
}

extern "C" void kernel_launch(void* const* d_in, const int* in_sizes, int n_in,
                              void* d_out, int out_size) {
    const float* x  = (const float*)d_in[0];
    const float* bf = (const float*)d_in[1];
    const float* cf = (const float*)d_in[2];
    const float* sf = (const float*)d_in[3];
    const float* hf = (const float*)d_in[4];
    float* out = (float*)d_out;

    const int nb = out_size / CHW;  // num_samples is 1 by shape constraints

    dim3 rgrid(RED_BLOCKS_PER_PLANE, nb);
    cr_reduce_kernel<<<rgrid, RED_THREADS>>>(x, bf);

    dim3 mgrid(MAIN_BLOCKS_PER_PLANE, nb);
    cr_main_kernel<<<mgrid, MAIN_THREADS>>>(x, bf, cf, sf, hf, out,
                                            (unsigned)(MAIN_BLOCKS_PER_PLANE * nb));
}

// round 6
// speedup vs baseline: 1.9214x; 1.2380x over previous
#include <cuda_runtime.h>
#include <cuda_bf16.h>

#define IMG_H 480
#define IMG_W 640
#define HW (IMG_H * IMG_W)          // 307200
#define CHW (3 * HW)
#define QPP (HW / 4)                // float4 quads per plane = 76800
#define RED_THREADS 256
#define RED_BLOCKS_PER_PLANE (QPP / (RED_THREADS * 2))   // 150, exact
#define MAIN_THREADS 256
#define MAIN_BLOCKS_PER_PLANE (QPP / MAIN_THREADS)       // 300, exact
#define MAX_B 64

// Scratch (device globals per harness rules).
// g_graysum starts zeroed (static init); the LAST main-kernel block to check
// in (after every block has read the mean) re-zeroes it for the next replay.
__device__ float g_graysum[MAX_B];
__device__ unsigned g_fin = 0;

__device__ __forceinline__ float quad_gray(const float4& r4, const float4& g4,
                                           const float4& b4, float B) {
    float s = 0.0f;
    float r, g, bl;
    #define ACC(comp) \
        r = __saturatef(r4.comp * B); \
        g = __saturatef(g4.comp * B); \
        bl = __saturatef(b4.comp * B); \
        s += 0.299f * r + 0.587f * g + 0.114f * bl;
    ACC(x) ACC(y) ACC(z) ACC(w)
    #undef ACC
    return s;
}

// Pass 1: per-batch gray sums, 2 quads/thread. Default cache policy so x
// becomes L2-resident for pass 2.
__global__ void __launch_bounds__(RED_THREADS)
cr_reduce_kernel(const float* __restrict__ x, const float* __restrict__ bf) {
    const int b = blockIdx.y;
    const int q0 = blockIdx.x * (RED_THREADS * 2) + threadIdx.x;  // exact fit
    const int q1 = q0 + RED_THREADS;
    const float4* base = (const float4*)(x + (size_t)b * CHW);

    const float B = bf[b];
    float4 r0 = base[q0];
    float4 g0 = base[q0 + QPP];
    float4 c0 = base[q0 + 2 * QPP];
    float4 r1 = base[q1];
    float4 g1 = base[q1 + QPP];
    float4 c1 = base[q1 + 2 * QPP];

    float s = quad_gray(r0, g0, c0, B) + quad_gray(r1, g1, c1, B);

    #pragma unroll
    for (int o = 16; o > 0; o >>= 1)
        s += __shfl_xor_sync(0xFFFFFFFFu, s, o);

    __shared__ float warp_s[RED_THREADS / 32];
    const int lane = threadIdx.x & 31;
    const int wid = threadIdx.x >> 5;
    if (lane == 0) warp_s[wid] = s;
    __syncthreads();
    if (wid == 0) {
        s = (lane < RED_THREADS / 32) ? warp_s[lane] : 0.0f;
        #pragma unroll
        for (int o = 4; o > 0; o >>= 1)
            s += __shfl_xor_sync(0xFFFFFFFFu, s, o);
        if (lane == 0) atomicAdd(&g_graysum[b], s);
    }
}

// Branchless fused pipeline. cm = (1-C)*mean is batch-uniform (hoisted).
__device__ __forceinline__ void process_px(float& r, float& g, float& b,
                                           float Bf, float Cf, float cm,
                                           float Sf, float hfv) {
    // brightness
    r = __saturatef(r * Bf);
    g = __saturatef(g * Bf);
    b = __saturatef(b * Bf);
    // contrast
    r = __saturatef(fmaf(Cf, r, cm));
    g = __saturatef(fmaf(Cf, g, cm));
    b = __saturatef(fmaf(Cf, b, cm));
    // saturation
    const float gray = 0.299f * r + 0.587f * g + 0.114f * b;
    const float sm = (1.0f - Sf) * gray;
    r = __saturatef(fmaf(Sf, r, sm));
    g = __saturatef(fmaf(Sf, g, sm));
    b = __saturatef(fmaf(Sf, b, sm));
    // hue rotation — branchless. Note v*s == chroma c identically, so the
    // saturation division disappears; output = v - c*clamp01(min(k, 4-k)),
    // k = (n + 6h) mod 6, n = 5/3/1 for r/g/b (continuous ≡ the case table).
    const float maxc = fmaxf(r, fmaxf(g, b));
    const float minc = fminf(r, fminf(g, b));
    const float c = maxc - minc;
    const float crd = (c == 0.0f) ? 1.0f : c;
    float num, base;
    if (maxc == r)      { num = g - b; base = 0.0f; }   // priority order kept
    else if (maxc == g) { num = b - r; base = 2.0f; }
    else                { num = r - g; base = 4.0f; }
    float h = (base + __fdividef(num, crd)) * (1.0f / 6.0f);
    h -= floorf(h);          // positive mod 1 (jnp semantics)
    h += hfv;
    h -= floorf(h);
    const float i6 = h * 6.0f;               // in [0, 6]
    float kr = i6 + 5.0f; kr = (kr >= 6.0f) ? kr - 6.0f : kr;
    float kg = i6 + 3.0f; kg = (kg >= 6.0f) ? kg - 6.0f : kg;
    float kb = i6 + 1.0f; kb = (kb >= 6.0f) ? kb - 6.0f : kb;
    r = fmaf(-c, __saturatef(fminf(kr, 4.0f - kr)), maxc);
    g = fmaf(-c, __saturatef(fminf(kg, 4.0f - kg)), maxc);
    b = fmaf(-c, __saturatef(fminf(kb, 4.0f - kb)), maxc);
}

// Pass 2: grid (MAIN_BLOCKS_PER_PLANE, nb) — exact fit. __ldcs reads (last
// touch, L2-resident from pass 1), __stcs writes (never re-read). Mean is
// broadcast via shared memory; the STS forces the global load to complete
// BEFORE this block's ticket, so the last ticket-holder can safely re-zero
// g_graysum while other blocks are still computing.
__global__ void __launch_bounds__(MAIN_THREADS)
cr_main_kernel(const float* __restrict__ x,
               const float* __restrict__ bf, const float* __restrict__ cf,
               const float* __restrict__ sf, const float* __restrict__ hf,
               float* __restrict__ out, unsigned total_blocks) {
    const int b = blockIdx.y;
    const int quad = blockIdx.x * MAIN_THREADS + threadIdx.x;

    __shared__ float sh_m;
    if (threadIdx.x == 0) sh_m = g_graysum[b];
    __syncthreads();     // BAR drains the STS → load completed before ticket
    if (threadIdx.x == 0) {
        const unsigned ticket = atomicAdd(&g_fin, 1u);
        if (ticket == total_blocks - 1u) {
            #pragma unroll
            for (int i = 0; i < MAX_B; i++) g_graysum[i] = 0.0f;
            g_fin = 0u;
            __threadfence();
        }
    }
    const float m = sh_m * (1.0f / (float)HW);

    const float4* inb = (const float4*)(x + (size_t)b * CHW);
    float4* outb = (float4*)(out + (size_t)b * CHW);

    const float B = bf[b];
    const float C = cf[b];
    const float S = sf[b];
    const float Hf = hf[b];
    const float cm = (1.0f - C) * m;

    float4 r4 = __ldcs(&inb[quad]);
    float4 g4 = __ldcs(&inb[quad + QPP]);
    float4 b4 = __ldcs(&inb[quad + 2 * QPP]);

    process_px(r4.x, g4.x, b4.x, B, C, cm, S, Hf);
    process_px(r4.y, g4.y, b4.y, B, C, cm, S, Hf);
    process_px(r4.z, g4.z, b4.z, B, C, cm, S, Hf);
    process_px(r4.w, g4.w, b4.w, B, C, cm, S, Hf);

    __stcs(&outb[quad],           r4);
    __stcs(&outb[quad + QPP],     g4);
    __stcs(&outb[quad + 2 * QPP], b4);
}

extern "C" void kernel_launch(void* const* d_in, const int* in_sizes, int n_in,
                              void* d_out, int out_size) {
    const float* x  = (const float*)d_in[0];
    const float* bf = (const float*)d_in[1];
    const float* cf = (const float*)d_in[2];
    const float* sf = (const float*)d_in[3];
    const float* hf = (const float*)d_in[4];
    float* out = (float*)d_out;

    const int nb = out_size / CHW;  // num_samples is 1 by shape constraints

    dim3 rgrid(RED_BLOCKS_PER_PLANE, nb);
    cr_reduce_kernel<<<rgrid, RED_THREADS>>>(x, bf);

    dim3 mgrid(MAIN_BLOCKS_PER_PLANE, nb);
    cr_main_kernel<<<mgrid, MAIN_THREADS>>>(x, bf, cf, sf, hf, out,
                                            (unsigned)(MAIN_BLOCKS_PER_PLANE * nb));
}